// round 16
// baseline (speedup 1.0000x reference)
#include <cuda_runtime.h>
#include <math.h>

#define NB 64
#define CC 64
#define TT 256
#define VV 25
#define SS 3
#define II 16

typedef unsigned long long ull;

// ---------------- device scratch ----------------
__device__ float g_A1 [NB*SS*VV*VV];
__device__ float g_Ai [NB*SS*VV*VV];
__device__ float g_y0 [NB*CC*TT*VV];   // ~105MB
__device__ float g_ST [NB*CC*VV];
__device__ float g_SVw[NB*CC*TT];
__device__ float g_gs [NB*VV];
__device__ float g_gt [NB*TT];
__device__ float g_gc [NB*CC];

__device__ __forceinline__ float sigm(float x) { return 1.0f / (1.0f + expf(-x)); }

// packed fp32x2 helpers
__device__ __forceinline__ ull pack2(float f) {
    ull r;
    asm("mov.b64 %0, {%1, %1};" : "=l"(r) : "r"(__float_as_uint(f)));
    return r;
}
__device__ __forceinline__ void fma2(ull& d, ull a, ull b) {
    asm("fma.rn.f32x2 %0, %1, %2, %0;" : "+l"(d) : "l"(a), "l"(b));
}
__device__ __forceinline__ float2 unpack2(ull p) {
    unsigned lo, hi;
    asm("mov.b64 {%0, %1}, %2;" : "=r"(lo), "=r"(hi) : "l"(p));
    return make_float2(__uint_as_float(lo), __uint_as_float(hi));
}

// ---------------- K0 ----------------
__global__ void k0_zero() {
    const int tot = NB*SS*VV*VV + NB*CC*VV;
    for (int i = blockIdx.x*blockDim.x + threadIdx.x; i < tot; i += gridDim.x*blockDim.x) {
        if (i < NB*SS*VV*VV) g_A1[i] = 0.f;
        else                 g_ST[i - NB*SS*VV*VV] = 0.f;
    }
}

// ---------------- K1: embeddings + partial A1 — j-PAIRED f32x2 ----------------
// grid (16, 64), 256 threads, dyn smem 99712 B
// Esp (ull): [s][16 jp-rows][t*28+v]; rows 0..7 = a-pairs, 8..15 = b-pairs.
// Each ull = (value for even j, value for odd j) at that (t,v).
__global__ __launch_bounds__(256) void k1_emb_adj(
    const float* __restrict__ x,  const float* __restrict__ Wa, const float* __restrict__ ba,
    const float* __restrict__ Wb, const float* __restrict__ bb)
{
    extern __shared__ float sm1[];
    float* Xs  = sm1;                       // 7168: [c][112] padded (pads 0)
    ull*   Esp = (ull*)(sm1 + 7168);        // 5376 ull (= 10752 floats)
    float* Wt3 = sm1 + 17920;               // 6912: [s][c][36-pad j] (j contiguous!)
    float* bs3 = sm1 + 24832;               // 96:   [s][32]

    const int tid = threadIdx.x;
    const int n   = blockIdx.y;

    // stage all weights once (j contiguous per (s,c) so f32x2 j-pairs are native)
    for (int i = tid; i < 6144; i += 256) {
        int s = i >> 11, r = i & 2047, j = r >> 6, c = r & 63;
        float w = (j < 16) ? Wa[(s*16 + j)*64 + c] : Wb[(s*16 + (j-16))*64 + c];
        Wt3[(s*64 + c)*36 + j] = w;
    }
    if (tid < 96) {
        int s = tid / 32, j = tid % 32;
        bs3[tid] = (j < 16) ? ba[s*16 + j] : bb[s*16 + (j-16)];
    }
    for (int i = tid; i < 768; i += 256) {
        int c = i / 12, r = i - c*12, tt = r / 3, k = r - tt*3;
        Xs[c*112 + tt*28 + 25 + k] = 0.f;
    }

    // A1 accumulators: per s, 4 w's, each ull = (even-j partial, odd-j partial)
    ull accW[SS][4];
    #pragma unroll
    for (int s = 0; s < SS; ++s)
        #pragma unroll
        for (int k = 0; k < 4; ++k) accW[s][k] = 0ULL;
    const bool hasA = tid < 175;
    const int  vA = tid / 7, w4A = tid % 7;

    // embed mapping: 224 threads = 8 jg x 28 quads (xo = t*7+v4)
    const bool hasE = tid < 224;
    const int  jg = tid / 28, xo = tid % 28;

    __syncthreads();

    for (int sub = 0; sub < 4; ++sub) {
        const int tile = blockIdx.x * 4 + sub;
        __syncthreads();   // prev readers of Xs/Esp done
        {   // load X tile into padded layout
            const float4* xg = (const float4*)x;
            for (int i = tid; i < 1600; i += 256) {
                int c = i / 25, qq = i - c*25;
                float4 v4 = xg[(n*64 + c)*1600 + tile*25 + qq];
                int j = qq*4;
                float vals[4] = {v4.x, v4.y, v4.z, v4.w};
                #pragma unroll
                for (int k = 0; k < 4; ++k) {
                    int tt = (j+k) / 25, v = (j+k) - tt*25;
                    Xs[c*112 + tt*28 + v] = vals[k];
                }
            }
        }
        __syncthreads();

        // embeddings: all 3 s, j-paired accumulators, X packed once per c
        if (hasE) {
            ull acc[SS][2][4];   // [s][pair p][v in quad]
            #pragma unroll
            for (int s = 0; s < SS; ++s) {
                const ull* bsp = (const ull*)(bs3 + s*32 + jg*4);
                ull b0 = bsp[0], b1 = bsp[1];
                #pragma unroll
                for (int k = 0; k < 4; ++k) { acc[s][0][k] = b0; acc[s][1][k] = b1; }
            }
            const float4* XsQ = (const float4*)Xs;  // quad index = c*28 + xo
            #pragma unroll 8
            for (int c = 0; c < 64; ++c) {
                float4 xq = XsQ[c*28 + xo];
                ull x0 = pack2(xq.x), x1 = pack2(xq.y), x2 = pack2(xq.z), x3 = pack2(xq.w);
                #pragma unroll
                for (int s = 0; s < SS; ++s) {
                    ulonglong2 wv = *(const ulonglong2*)(Wt3 + (s*64 + c)*36 + jg*4);
                    fma2(acc[s][0][0], wv.x, x0); fma2(acc[s][0][1], wv.x, x1);
                    fma2(acc[s][0][2], wv.x, x2); fma2(acc[s][0][3], wv.x, x3);
                    fma2(acc[s][1][0], wv.y, x0); fma2(acc[s][1][1], wv.y, x1);
                    fma2(acc[s][1][2], wv.y, x2); fma2(acc[s][1][3], wv.y, x3);
                }
            }
            #pragma unroll
            for (int s = 0; s < SS; ++s) {
                #pragma unroll
                for (int p = 0; p < 2; ++p) {
                    // row: a-pairs (jg<4) land at 0..7, b-pairs (jg>=4) at 8..15
                    ulonglong2* dst = (ulonglong2*)(Esp + (s*16 + jg*2 + p)*112 + xo*4);
                    dst[0] = make_ulonglong2(acc[s][p][0], acc[s][p][1]);
                    dst[1] = make_ulonglong2(acc[s][p][2], acc[s][p][3]);
                }
            }
        }
        __syncthreads();

        // A1 partial: pair-parallel over j; lo/hi accumulate even/odd j
        if (hasA) {
            #pragma unroll
            for (int s = 0; s < SS; ++s) {
                const ull* Ea = Esp + (s*16)*112;         // a-pair rows
                const ull* Eb = Esp + (s*16 + 8)*112;     // b-pair rows
                ull a0 = accW[s][0], a1 = accW[s][1], a2 = accW[s][2], a3 = accW[s][3];
                #pragma unroll 4
                for (int jp = 0; jp < 8; ++jp) {
                    #pragma unroll
                    for (int t = 0; t < 4; ++t) {
                        ull ap = Ea[jp*112 + t*28 + vA];
                        const ulonglong2* bp =
                            (const ulonglong2*)(Eb + jp*112 + t*28 + w4A*4);
                        ulonglong2 b01 = bp[0], b23 = bp[1];
                        fma2(a0, ap, b01.x); fma2(a1, ap, b01.y);
                        fma2(a2, ap, b23.x); fma2(a3, ap, b23.y);
                    }
                }
                accW[s][0] = a0; accW[s][1] = a1; accW[s][2] = a2; accW[s][3] = a3;
            }
        }
    }

    if (hasA) {
        #pragma unroll
        for (int s = 0; s < SS; ++s) {
            float* dst = &g_A1[((n*SS + s)*VV + vA)*VV];
            #pragma unroll
            for (int k = 0; k < 4; ++k) {
                float2 f = unpack2(accW[s][k]);
                int w = w4A*4 + k;
                if (w < VV) atomicAdd(&dst[w], f.x + f.y);   // fold even-j + odd-j
            }
        }
    }
}

// ---------------- K2 ----------------
__global__ void k2_adj(const float* __restrict__ PA, const float* __restrict__ alpha) {
    const float al = alpha[0];
    const int tot = NB*SS*VV*VV;
    for (int i = blockIdx.x*blockDim.x + threadIdx.x; i < tot; i += gridDim.x*blockDim.x)
        g_Ai[i] = PA[i % (SS*VV*VV)] + al * tanhf(g_A1[i] * (1.0f/4096.0f));
}

// ---------------- K3: fused (Wd@X)@Ai — o-PAIR per thread ----------------
// grid (64, 64), 128 threads, dyn smem 48128 B, 3 blocks/SM
__global__ __launch_bounds__(128, 3) void k3_main(
    const float* __restrict__ x,  const float* __restrict__ Wd, const float* __restrict__ bd,
    const float* __restrict__ gamma, const float* __restrict__ beta)
{
    extern __shared__ float sm[];
    float* Xs  = sm;            // 7168: [c][t*28+v] padded
    float* Ais = sm + 7168;     // 704:  [25][28] pad cols zeroed
    float* Wds = sm + 7872;     // 4160: [c][65-pad o]

    const int tid  = threadIdx.x;
    const int n    = blockIdx.y;
    const int tile = blockIdx.x;        // t0 = tile*4
    const int o0   = tid & 31;
    const int o1   = o0 + 32;
    const int t    = tid >> 5;          // one t per warp

    if (tid < 25) { Ais[tid*28+25] = 0.f; Ais[tid*28+26] = 0.f; Ais[tid*28+27] = 0.f; }
    for (int i = tid; i < 768; i += 128) {
        int c = i / 12, r = i - c*12, tt = r / 3, k = r - tt*3;
        Xs[c*112 + tt*28 + 25 + k] = 0.f;
    }
    {
        const float4* xg = (const float4*)x;
        for (int i = tid; i < 1600; i += 128) {
            int c = i / 25, qq = i - c*25;
            float4 v4 = xg[(n*64 + c)*1600 + tile*25 + qq];
            int j = qq*4;
            float vals[4] = {v4.x, v4.y, v4.z, v4.w};
            #pragma unroll
            for (int k = 0; k < 4; ++k) {
                int tt = (j+k) / 25, v = (j+k) - tt*25;
                Xs[c*112 + tt*28 + v] = vals[k];
            }
        }
    }

    ull Y0[14], Y1[14];
    #pragma unroll
    for (int k = 0; k < 14; ++k) { Y0[k] = 0ULL; Y1[k] = 0ULL; }

    for (int s = 0; s < SS; ++s) {
        __syncthreads();
        for (int i = tid; i < 625; i += 128) Ais[(i/25)*28 + (i%25)] = g_Ai[(n*SS + s)*625 + i];
        for (int i = tid; i < 4096; i += 128) {
            int oo = i >> 6, c = i & 63;
            Wds[c*65 + oo] = Wd[s*4096 + i];
        }
        __syncthreads();

        ull U0[14], U1[14];
        #pragma unroll
        for (int k = 0; k < 14; ++k) { U0[k] = 0ULL; U1[k] = 0ULL; }
        {
            const float* xb = Xs + t*28;
            #pragma unroll 8
            for (int c = 0; c < 64; ++c) {
                ull w0 = pack2(Wds[c*65 + o0]);
                ull w1 = pack2(Wds[c*65 + o1]);
                const ulonglong2* xp = (const ulonglong2*)(xb + c*112);
                #pragma unroll
                for (int w4 = 0; w4 < 7; ++w4) {
                    ulonglong2 xv = xp[w4];
                    fma2(U0[2*w4], w0, xv.x); fma2(U0[2*w4+1], w0, xv.y);
                    fma2(U1[2*w4], w1, xv.x); fma2(U1[2*w4+1], w1, xv.y);
                }
            }
        }

        #pragma unroll
        for (int v = 0; v < 25; ++v) {
            float2 fu0 = unpack2(U0[v >> 1]);
            float2 fu1 = unpack2(U1[v >> 1]);
            ull uv0 = pack2((v & 1) ? fu0.y : fu0.x);
            ull uv1 = pack2((v & 1) ? fu1.y : fu1.x);
            const ulonglong2* ap = (const ulonglong2*)(Ais + v*28);
            #pragma unroll
            for (int w4 = 0; w4 < 7; ++w4) {
                ulonglong2 av = ap[w4];
                fma2(Y0[2*w4], uv0, av.x); fma2(Y0[2*w4+1], uv0, av.y);
                fma2(Y1[2*w4], uv1, av.x); fma2(Y1[2*w4+1], uv1, av.y);
            }
        }
    }

    float ya[28], yb[28];
    #pragma unroll
    for (int k = 0; k < 14; ++k) {
        float2 f0 = unpack2(Y0[k]); ya[2*k] = f0.x; ya[2*k+1] = f0.y;
        float2 f1 = unpack2(Y1[k]); yb[2*k] = f1.x; yb[2*k+1] = f1.y;
    }
    {
        const float scl  = rsqrtf(1.0f + 1e-5f);
        const float bsA = bd[o0] + bd[64+o0] + bd[128+o0];
        const float bsB = bd[o1] + bd[64+o1] + bd[128+o1];
        const float scA = gamma[o0]*scl, scB = gamma[o1]*scl;
        const float btA = beta[o0],      btB = beta[o1];
        const float* xrA = Xs + o0*112 + t*28;
        const float* xrB = Xs + o1*112 + t*28;
        #pragma unroll
        for (int w = 0; w < 25; ++w) {
            ya[w] = fmaxf((ya[w] + bsA)*scA + btA + xrA[w], 0.f);
            yb[w] = fmaxf((yb[w] + bsB)*scB + btB + xrB[w], 0.f);
        }
    }
    __syncthreads();
    #pragma unroll
    for (int w = 0; w < 25; ++w) {
        Xs[o0*100 + t*25 + w] = ya[w];
        Xs[o1*100 + t*25 + w] = yb[w];
    }
    __syncthreads();

    {
        float4* yg = (float4*)g_y0;
        const float4* Xs4 = (const float4*)Xs;
        for (int i = tid; i < 1600; i += 128) {
            int c = i / 25, qq = i - c*25;
            yg[(n*64 + c)*1600 + tile*25 + qq] = Xs4[c*25 + qq];
        }
        for (int i = tid; i < 1600; i += 128) {
            int c = i / 25, v = i - c*25;
            float ssum = Xs[c*100 + v] + Xs[c*100 + 25 + v]
                       + Xs[c*100 + 50 + v] + Xs[c*100 + 75 + v];
            atomicAdd(&g_ST[n*1600 + i], ssum);
        }
    }
}

// ---------------- K4: spatial gate ----------------
__global__ __launch_bounds__(128) void k4_sgate(const float* __restrict__ Wsa,
                                                const float* __restrict__ bsa)
{
    __shared__ float se[1600];
    __shared__ float wk[1600];
    const int tid = threadIdx.x, n = blockIdx.x;
    for (int i = tid; i < 1600; i += 128) {
        se[i] = g_ST[n*1600 + i] * (1.0f/256.0f);
        wk[i] = Wsa[i];
    }
    __syncthreads();
    if (tid < VV) {
        int v = tid;
        float acc = bsa[0];
        for (int c = 0; c < 64; ++c)
            #pragma unroll
            for (int k = 0; k < 25; ++k) {
                int u = v + k - 12;
                if (u >= 0 && u < 25) acc += wk[c*25 + k] * se[c*25 + u];
            }
        g_gs[n*25 + v] = 1.0f + sigm(acc);
    }
}

// ---------------- K5: SVw = sum_v y0*(1+gs) — coalesced smem staging ----------------
__global__ __launch_bounds__(256) void k5_svw() {
    __shared__ float gs[25];
    __shared__ __align__(16) float ys[6400];
    const int bid = blockIdx.x;
    const int n = bid >> 6, c = bid & 63;
    const int tid = threadIdx.x;
    if (tid < 25) gs[tid] = g_gs[n*25 + tid];
    {
        const float4* yg = ((const float4*)g_y0) + (n*64 + c)*1600;
        float4* ys4 = (float4*)ys;
        for (int i = tid; i < 1600; i += 256) ys4[i] = yg[i];
    }
    __syncthreads();
    const float* row = ys + tid*25;
    float s = 0.f;
    #pragma unroll
    for (int v = 0; v < 25; ++v) s += row[v] * gs[v];
    g_SVw[(n*64 + c)*256 + tid] = s;
}

// ---------------- K6: temporal gate ----------------
__global__ __launch_bounds__(256) void k6_tgate(const float* __restrict__ Wta,
                                                const float* __restrict__ bta)
{
    __shared__ float wk[576];
    const int tid = threadIdx.x, n = blockIdx.x;
    for (int i = tid; i < 576; i += 256) wk[i] = Wta[i];
    __syncthreads();
    const int t = tid;
    float s = 0.f;
    for (int c = 0; c < 64; ++c) {
        const float* sv = &g_SVw[(n*64 + c)*256];
        #pragma unroll
        for (int k = 0; k < 9; ++k) {
            int u = t + k - 4;
            if (u >= 0 && u < 256) s += wk[c*9 + k] * sv[u];
        }
    }
    float acc = bta[0] + s * (1.0f/25.0f);
    g_gt[n*256 + t] = 1.0f + sigm(acc);
}

// ---------------- K7: channel gate ----------------
__global__ __launch_bounds__(64) void k7_cgate(
    const float* __restrict__ W1, const float* __restrict__ b1,
    const float* __restrict__ W2, const float* __restrict__ b2)
{
    __shared__ float gt[256];
    __shared__ float se[64];
    __shared__ float h[32];
    const int tid = threadIdx.x, n = blockIdx.x;
    for (int i = tid; i < 256; i += 64) gt[i] = g_gt[n*256 + i];
    __syncthreads();
    {
        const float* sv = &g_SVw[(n*64 + tid)*256];
        float s = 0.f;
        for (int t = 0; t < 256; ++t) s += sv[t] * gt[t];
        se[tid] = s * (1.0f/6400.0f);
    }
    __syncthreads();
    if (tid < 32) {
        float a = b1[tid];
        for (int c = 0; c < 64; ++c) a += W1[tid*64 + c] * se[c];
        h[tid] = fmaxf(a, 0.f);
    }
    __syncthreads();
    {
        float a = b2[tid];
        #pragma unroll
        for (int j = 0; j < 32; ++j) a += W2[tid*32 + j] * h[j];
        g_gc[n*64 + tid] = 1.0f + sigm(a);
    }
}

// ---------------- K8: finalize ----------------
__global__ __launch_bounds__(256) void k8_final(float* __restrict__ out) {
    const int i4 = blockIdx.x*256 + threadIdx.x;
    if (i4 >= NB*CC*TT*VV/4) return;
    float4 y = ((const float4*)g_y0)[i4];
    float r[4] = {y.x, y.y, y.z, y.w};
    #pragma unroll
    for (int k = 0; k < 4; ++k) {
        unsigned idx = (unsigned)i4*4u + k;
        unsigned row = idx / 25u;
        unsigned v   = idx - row*25u;
        unsigned t   = row & 255u;
        unsigned nc  = row >> 8;
        unsigned n   = nc >> 6;
        r[k] *= g_gs[n*25 + v] * g_gt[n*256 + t] * g_gc[nc];
    }
    ((float4*)out)[i4] = make_float4(r[0], r[1], r[2], r[3]);
}

// ---------------- launch ----------------
extern "C" void kernel_launch(void* const* d_in, const int* in_sizes, int n_in,
                              void* d_out, int out_size) {
    const float* x     = (const float*)d_in[0];
    const float* PA    = (const float*)d_in[1];
    const float* alpha = (const float*)d_in[2];
    const float* Wa    = (const float*)d_in[3];
    const float* ba    = (const float*)d_in[4];
    const float* Wb    = (const float*)d_in[5];
    const float* bb    = (const float*)d_in[6];
    const float* Wd    = (const float*)d_in[7];
    const float* bd    = (const float*)d_in[8];
    const float* gam   = (const float*)d_in[9];
    const float* bet   = (const float*)d_in[10];
    const float* Wsa   = (const float*)d_in[11];
    const float* bsa   = (const float*)d_in[12];
    const float* Wta   = (const float*)d_in[13];
    const float* bta   = (const float*)d_in[14];
    const float* W1    = (const float*)d_in[15];
    const float* b1    = (const float*)d_in[16];
    const float* W2    = (const float*)d_in[17];
    const float* b2    = (const float*)d_in[18];
    float* out = (float*)d_out;

    cudaFuncSetAttribute(k1_emb_adj, cudaFuncAttributeMaxDynamicSharedMemorySize, 100352);
    cudaFuncSetAttribute(k3_main,    cudaFuncAttributeMaxDynamicSharedMemorySize, 49152);

    k0_zero<<<224, 1024>>>();
    k1_emb_adj<<<dim3(16, 64), 256, 99712>>>(x, Wa, ba, Wb, bb);
    k2_adj<<<120, 1024>>>(PA, alpha);
    k3_main<<<dim3(64, 64), 128, 48128>>>(x, Wd, bd, gam, bet);
    k4_sgate<<<64, 128>>>(Wsa, bsa);
    k5_svw<<<4096, 256>>>();
    k6_tgate<<<64, 256>>>(Wta, bta);
    k7_cgate<<<64, 64>>>(W1, b1, W2, b2);
    k8_final<<<25600, 256>>>(out);
}